// round 16
// baseline (speedup 1.0000x reference)
#include <cuda_runtime.h>
#include <math_constants.h>

#define B_   4
#define C_   84
#define CR_  80          // channels in the max (84 - 4)
#define H_   512
#define W_   512
#define HW_  (H_ * W_)

#define CW   64          // columns per block strip
#define TH   8           // output rows per block
#define NQ   4           // warp q: probs-ch [q*20,+20), store-ch [q*21,+21)
#define PPQ  20
#define CPQ  21
#define NT   128
#define RING 4

// ---------------------------------------------------------------------------
// Fused NMS, fully-vectorized (512B warp transactions), reload-based store.
//
// Block = 64-col x 8-row strip. Warp-load pairing: lanes 0-15 carry channel
// c (cols 4*lx..4*lx+3), lanes 16-31 carry channel c+1 — one LDG.128 moves
// 2 channels x 64 cols = 512B in two dense 256B segments.
//
// Per output row h (ONE barrier):
//   probs_row(h+1): warp q max-reduces its 20 probs channels (10 paired
//     float4 loads), cross-half shuffle -> per-quarter per-col float4 maxes
//     in pbq ring slot (h+1)&3. Warps 0/1 gather the two halo-column 80-ch
//     maxes (scalar, L2-hot from neighbor strips) -> ph. Pad rows -> 0.
//   __syncthreads();
//   combine+mask row h: quarter-combine in registers (12 LDS.128), strip-
//     internal neighbors via shuffles, strip-edge via ph. Reference
//     semantics: strict > for row-above + left, >= for right + row-below;
//     zero padding.
//   store row h: re-read 21 channels as paired float4 (lines touched by
//     probs_row one iteration ago -> L2-resident; reuse window ~74MB < L2),
//     multiply by mask, streaming stores.
//
// Ring safety (R13 argument, RING=4): iter h writes slot (h+1)&3 pre-barrier
// in warp-private regions, reads slots (h-1..h+1)&3 post-barrier; a fast
// warp's next write hits (h+2)&3 — disjoint. One barrier per row suffices.
// ---------------------------------------------------------------------------
__global__ void __launch_bounds__(NT, 8) fused_nms_vec(
    const float* __restrict__ points, float* __restrict__ out)
{
    __shared__ float4 pbq[RING][NQ][CW / 4];  // per-quarter per-col maxes
    __shared__ float  ph[RING][2];            // halo-column combined maxes

    const int tid  = threadIdx.x;
    const int q    = tid >> 5;                // warp = channel quarter
    const int lane = tid & 31;
    const int half = lane >> 4;               // channel-pair half
    const int lx   = lane & 15;               // float4 group: cols 4lx..4lx+3
    const int x0   = blockIdx.x * CW;
    const int h0   = blockIdx.y * TH;
    const int b    = blockIdx.z;
    const size_t bbase = (size_t)b * C_ * HW_;

    const float* inb  = points + bbase + x0 + 4 * lx;
    float*       outb = out    + bbase + x0 + 4 * lx;

    // ---- probs for row g -> ring slot g&3 -------------------------------
    auto probs_row = [&](int g) {
        const int s = g & (RING - 1);
        float4 m4 = make_float4(0.f, 0.f, 0.f, 0.f);   // pad value
        if (g >= 0 && g < H_) {
            m4 = make_float4(-CUDART_INF_F, -CUDART_INF_F,
                             -CUDART_INF_F, -CUDART_INF_F);
            const float* rp = inb + (size_t)g * W_;
            #pragma unroll
            for (int i = 0; i < PPQ / 2; i++) {
                const int c = q * PPQ + 2 * i + half;
                float4 v = __ldg(reinterpret_cast<const float4*>(
                                     rp + (size_t)c * HW_));
                m4.x = fmaxf(m4.x, v.x);
                m4.y = fmaxf(m4.y, v.y);
                m4.z = fmaxf(m4.z, v.z);
                m4.w = fmaxf(m4.w, v.w);
            }
        }
        // combine the two channel-halves (lanes l <-> l^16 share columns)
        m4.x = fmaxf(m4.x, __shfl_xor_sync(0xffffffffu, m4.x, 16));
        m4.y = fmaxf(m4.y, __shfl_xor_sync(0xffffffffu, m4.y, 16));
        m4.z = fmaxf(m4.z, __shfl_xor_sync(0xffffffffu, m4.z, 16));
        m4.w = fmaxf(m4.w, __shfl_xor_sync(0xffffffffu, m4.w, 16));
        if (half == 0) pbq[s][q][lx] = m4;

        // halo columns: warp0 -> x0-1, warp1 -> x0+CW (80-ch scalar gather)
        if (q < 2) {
            const int hx = (q == 0) ? (x0 - 1) : (x0 + CW);
            float hm = 0.f;
            if (g >= 0 && g < H_ && hx >= 0 && hx < W_) {
                hm = -CUDART_INF_F;
                const float* hp = points + bbase + (size_t)g * W_ + hx;
                #pragma unroll
                for (int k = 0; k < 3; k++) {
                    const int c = lane + k * 32;
                    if (c < CR_) hm = fmaxf(hm, __ldg(hp + (size_t)c * HW_));
                }
                #pragma unroll
                for (int off = 16; off; off >>= 1)
                    hm = fmaxf(hm, __shfl_xor_sync(0xffffffffu, hm, off));
            }
            if (lane == 0) ph[s][q] = hm;
        }
    };

    // quarter-combined probs float4 for ring slot s at this lane's 4 cols
    auto qmax = [&](int s) -> float4 {
        float4 a = pbq[s][0][lx], c = pbq[s][1][lx];
        float4 d = pbq[s][2][lx], e = pbq[s][3][lx];
        float4 r;
        r.x = fmaxf(fmaxf(a.x, c.x), fmaxf(d.x, e.x));
        r.y = fmaxf(fmaxf(a.y, c.y), fmaxf(d.y, e.y));
        r.z = fmaxf(fmaxf(a.z, c.z), fmaxf(d.z, e.z));
        r.w = fmaxf(fmaxf(a.w, c.w), fmaxf(d.w, e.w));
        return r;
    };

    // ---- prologue ---------------------------------------------------------
    probs_row(h0 - 1);
    probs_row(h0);

    // ---- main pipeline: one barrier per row -------------------------------
    for (int h = h0; h < h0 + TH; h++) {
        probs_row(h + 1);
        __syncthreads();

        const int s0 = (h - 1) & (RING - 1);
        const int s1 = h       & (RING - 1);
        const int s2 = (h + 1) & (RING - 1);

        // combined rows as 6-wide arrays: [0]=left nb, [1..4]=cols, [5]=right
        float a0[6], a1[6], a2[6];
        {
            float4 c0 = qmax(s0), c1 = qmax(s1), c2 = qmax(s2);
            a0[1] = c0.x; a0[2] = c0.y; a0[3] = c0.z; a0[4] = c0.w;
            a1[1] = c1.x; a1[2] = c1.y; a1[3] = c1.z; a1[4] = c1.w;
            a2[1] = c2.x; a2[2] = c2.y; a2[3] = c2.z; a2[4] = c2.w;
            // strip-internal neighbors via shuffle; edges via ph
            float l0 = __shfl_up_sync(0xffffffffu, c0.w, 1);
            float l1 = __shfl_up_sync(0xffffffffu, c1.w, 1);
            float l2 = __shfl_up_sync(0xffffffffu, c2.w, 1);
            float r0 = __shfl_down_sync(0xffffffffu, c0.x, 1);
            float r1 = __shfl_down_sync(0xffffffffu, c1.x, 1);
            float r2 = __shfl_down_sync(0xffffffffu, c2.x, 1);
            a0[0] = (lx == 0)  ? ph[s0][0] : l0;
            a1[0] = (lx == 0)  ? ph[s1][0] : l1;
            a2[0] = (lx == 0)  ? ph[s2][0] : l2;
            a0[5] = (lx == 15) ? ph[s0][1] : r0;
            a1[5] = (lx == 15) ? ph[s1][1] : r1;
            a2[5] = (lx == 15) ? ph[s2][1] : r2;
        }

        float4 mk;
        {
            float m[4];
            #pragma unroll
            for (int j = 0; j < 4; j++) {
                const float p = a1[j + 1];
                bool ok =
                    (p >  a0[j    ]) &&   // (-1,-1)
                    (p >  a0[j + 1]) &&   // (-1, 0)
                    (p >  a0[j + 2]) &&   // (-1,+1)
                    (p >  a1[j    ]) &&   // ( 0,-1) left
                    (p >= a1[j + 2]) &&   // ( 0,+1) right
                    (p >= a2[j    ]) &&   // (+1,-1)
                    (p >= a2[j + 1]) &&   // (+1, 0)
                    (p >= a2[j + 2]);     // (+1,+1)
                m[j] = ok ? 1.0f : 0.0f;
            }
            mk = make_float4(m[0], m[1], m[2], m[3]);
        }

        // ---- store row h: paired float4 reload (L2-hot) * mask -----------
        const float* ip = inb  + (size_t)h * W_;
        float*       op = outb + (size_t)h * W_;
        #pragma unroll
        for (int i = 0; i < 10; i++) {
            const size_t o = (size_t)(q * CPQ + 2 * i + half) * HW_;
            float4 v = __ldg(reinterpret_cast<const float4*>(ip + o));
            v.x *= mk.x; v.y *= mk.y; v.z *= mk.z; v.w *= mk.w;
            __stcs(reinterpret_cast<float4*>(op + o), v);
        }
        if (half == 0) {                       // 21st channel of this quarter
            const size_t o = (size_t)(q * CPQ + 20) * HW_;
            float4 v = __ldg(reinterpret_cast<const float4*>(ip + o));
            v.x *= mk.x; v.y *= mk.y; v.z *= mk.z; v.w *= mk.w;
            __stcs(reinterpret_cast<float4*>(op + o), v);
        }
        // next iteration's probs_row writes slot (h+2)&3 — disjoint from the
        // three slots read above; warp-private writes; 1 barrier/row is safe.
    }
}

// ---------------------------------------------------------------------------
extern "C" void kernel_launch(void* const* d_in, const int* in_sizes, int n_in,
                              void* d_out, int out_size)
{
    const float* points = (const float*)d_in[0];
    float* out = (float*)d_out;

    dim3 grid(W_ / CW, H_ / TH, B_);   // (8, 64, 4) = 2048 blocks
    fused_nms_vec<<<grid, NT>>>(points, out);
}